// round 4
// baseline (speedup 1.0000x reference)
#include <cuda_runtime.h>
#include <cuda_bf16.h>
#include <stdint.h>

#define NHEAD 8
#define SLEN 2048
#define SCALE 0.17677669529663689f
#define LOG2E 1.4426950408889634f

// ------------- device scratch (no allocation allowed) -------------
static __device__ __nv_bfloat16 g_Qhi[NHEAD][SLEN][32], g_Qlo[NHEAD][SLEN][32];
static __device__ __nv_bfloat16 g_Khi[NHEAD][SLEN][32], g_Klo[NHEAD][SLEN][32];
static __device__ __nv_bfloat16 g_Vthi[NHEAD][32][SLEN], g_Vtlo[NHEAD][32][SLEN];
static __device__ float g_G[NHEAD][SLEN][32];
static __device__ float g_AO[SLEN][256];

// ------------- helpers -------------
__device__ __forceinline__ unsigned long long dup2(float x) {
    unsigned long long r; asm("mov.b64 %0, {%1,%1};" : "=l"(r) : "f"(x)); return r;
}
__device__ __forceinline__ unsigned long long pk2(float2 v) {
    unsigned long long r; asm("mov.b64 %0, {%1,%2};" : "=l"(r) : "f"(v.x), "f"(v.y)); return r;
}
__device__ __forceinline__ void fma2(unsigned long long &d, unsigned long long a, unsigned long long b) {
    asm("fma.rn.f32x2 %0, %1, %2, %0;" : "+l"(d) : "l"(a), "l"(b));
}
__device__ __forceinline__ float2 unpack2(unsigned long long v) {
    float2 r; asm("mov.b64 {%0,%1}, %2;" : "=f"(r.x), "=f"(r.y) : "l"(v)); return r;
}
__device__ __forceinline__ float ex2f(float x) {
    float y; asm("ex2.approx.f32 %0, %1;" : "=f"(y) : "f"(x)); return y;
}
// pack: low 16 bits = bf16(lo), high = bf16(hi)
__device__ __forceinline__ uint32_t packbf(float lo, float hi) {
    uint32_t r; asm("cvt.rn.bf16x2.f32 %0, %1, %2;" : "=r"(r) : "f"(hi), "f"(lo)); return r;
}
__device__ __forceinline__ void splitp(float x, float y, uint32_t &hi, uint32_t &lo) {
    hi = packbf(x, y);
    float xh = __uint_as_float(hi << 16);
    float yh = __uint_as_float(hi & 0xffff0000u);
    lo = packbf(x - xh, y - yh);
}
__device__ __forceinline__ void mma_bf16(float* d, const uint32_t* a, uint32_t b0, uint32_t b1) {
    asm volatile("mma.sync.aligned.m16n8k16.row.col.f32.bf16.bf16.f32 "
        "{%0,%1,%2,%3},{%4,%5,%6,%7},{%8,%9},{%0,%1,%2,%3};"
        : "+f"(d[0]), "+f"(d[1]), "+f"(d[2]), "+f"(d[3])
        : "r"(a[0]), "r"(a[1]), "r"(a[2]), "r"(a[3]), "r"(b0), "r"(b1));
}

// =============== kernel 1: input projections (fp32 f32x2) ===============
// z=0: Xq @ Wq + Bq -> Q (bf16 split, pre-scaled), sigmoid(G)
// z=1: Xkv @ Wk + Bk -> K (split), V (split, transposed)
__global__ __launch_bounds__(128) void proj_kernel(
    const float* __restrict__ Xq, const float* __restrict__ Xkv,
    const float* __restrict__ Wq, const float* __restrict__ Wk,
    const float* __restrict__ Bq, const float* __restrict__ Bk)
{
    __shared__ float As[64][17];
    __shared__ float Bs[16][64];
    const int z = blockIdx.z;
    const float* __restrict__ X  = z ? Xkv : Xq;
    const float* __restrict__ W  = z ? Wk  : Wq;
    const float* __restrict__ Bv = z ? Bk  : Bq;
    const int m0 = blockIdx.y * 64, n0b = blockIdx.x * 64;
    const int tid = threadIdx.x, tx = tid & 15, ty = tid >> 4;

    unsigned long long acc[8][2];
#pragma unroll
    for (int i = 0; i < 8; i++) { acc[i][0] = 0ull; acc[i][1] = 0ull; }

    for (int kt = 0; kt < 256; kt += 16) {
        __syncthreads();
#pragma unroll
        for (int p = 0; p < 2; p++) {
            int e = tid + p * 128, r = e >> 2, kq = e & 3;
            float4 f = *(const float4*)&X[(m0 + r) * 256 + kt + kq * 4];
            As[r][kq * 4 + 0] = f.x; As[r][kq * 4 + 1] = f.y;
            As[r][kq * 4 + 2] = f.z; As[r][kq * 4 + 3] = f.w;
        }
#pragma unroll
        for (int p = 0; p < 2; p++) {
            int e = tid + p * 128, k = e >> 4, nq = e & 15;
            *(float4*)&Bs[k][nq * 4] = *(const float4*)&W[(kt + k) * 512 + n0b + nq * 4];
        }
        __syncthreads();
#pragma unroll
        for (int k = 0; k < 16; k++) {
            unsigned long long b0 = pk2(*(const float2*)&Bs[k][tx * 4]);
            unsigned long long b1 = pk2(*(const float2*)&Bs[k][tx * 4 + 2]);
#pragma unroll
            for (int i = 0; i < 8; i++) {
                unsigned long long a = dup2(As[ty * 8 + i][k]);
                fma2(acc[i][0], a, b0);
                fma2(acc[i][1], a, b1);
            }
        }
    }
#pragma unroll
    for (int i = 0; i < 8; i++) {
        int q = m0 + ty * 8 + i;
#pragma unroll
        for (int j = 0; j < 2; j++) {
            float2 v = unpack2(acc[i][j]);
            float vv[2] = { v.x, v.y };
#pragma unroll
            for (int e = 0; e < 2; e++) {
                int col = n0b + tx * 4 + j * 2 + e;
                int h = col >> 6, cc = col & 63;
                float x = vv[e] + Bv[col];
                if (z == 0) {
                    if (cc < 32) {
                        float s = x * SCALE;
                        __nv_bfloat16 hi = __float2bfloat16(s);
                        g_Qhi[h][q][cc] = hi;
                        g_Qlo[h][q][cc] = __float2bfloat16(s - __bfloat162float(hi));
                    } else {
                        g_G[h][q][cc - 32] = 1.0f / (1.0f + __expf(-x));
                    }
                } else {
                    __nv_bfloat16 hi = __float2bfloat16(x);
                    float lo = x - __bfloat162float(hi);
                    if (cc < 32) {
                        g_Khi[h][q][cc] = hi; g_Klo[h][q][cc] = __float2bfloat16(lo);
                    } else {
                        g_Vthi[h][cc - 32][q] = hi; g_Vtlo[h][cc - 32][q] = __float2bfloat16(lo);
                    }
                }
            }
        }
    }
}

// =============== kernel 2: flash attention (split-bf16 MMA) ===============
__global__ __launch_bounds__(128) void attn_kernel(const float* __restrict__ bias)
{
    __shared__ __nv_bfloat16 Kh[64][40], Kl[64][40];
    __shared__ __nv_bfloat16 Vh[32][72], Vl[32][72];
    const int h = blockIdx.y;
    const int tid = threadIdx.x, wid = tid >> 5, ln = tid & 31;
    const int q0 = blockIdx.x * 64 + wid * 16;
    const int r0 = ln >> 2, c0 = (ln & 3) * 2;

    // Q fragments (hi/lo), 2 k-chunks of 16
    uint32_t qh[2][4], ql[2][4];
#pragma unroll
    for (int kc = 0; kc < 2; kc++) {
        qh[kc][0] = *(const uint32_t*)&g_Qhi[h][q0 + r0][kc * 16 + c0];
        qh[kc][1] = *(const uint32_t*)&g_Qhi[h][q0 + r0 + 8][kc * 16 + c0];
        qh[kc][2] = *(const uint32_t*)&g_Qhi[h][q0 + r0][kc * 16 + c0 + 8];
        qh[kc][3] = *(const uint32_t*)&g_Qhi[h][q0 + r0 + 8][kc * 16 + c0 + 8];
        ql[kc][0] = *(const uint32_t*)&g_Qlo[h][q0 + r0][kc * 16 + c0];
        ql[kc][1] = *(const uint32_t*)&g_Qlo[h][q0 + r0 + 8][kc * 16 + c0];
        ql[kc][2] = *(const uint32_t*)&g_Qlo[h][q0 + r0][kc * 16 + c0 + 8];
        ql[kc][3] = *(const uint32_t*)&g_Qlo[h][q0 + r0 + 8][kc * 16 + c0 + 8];
    }

    float o[4][4];
#pragma unroll
    for (int n = 0; n < 4; n++)
#pragma unroll
        for (int j = 0; j < 4; j++) o[n][j] = 0.0f;
    float mr[2] = { -1e30f, -1e30f };
    float lr[2] = { 0.0f, 0.0f };

    for (int kt = 0; kt < SLEN; kt += 64) {
        __syncthreads();
        // K tile: 64 rows x 32 cols bf16 = 256 uint4 transfers (FIXED indexing)
#pragma unroll
        for (int p = 0; p < 2; p++) {
            int e = tid + p * 128, r = e >> 2, c = (e & 3) * 8;
            *(uint4*)&Kh[r][c] = *(const uint4*)&g_Khi[h][kt + r][c];
            *(uint4*)&Kl[r][c] = *(const uint4*)&g_Klo[h][kt + r][c];
        }
        // V^T tile: 32 rows x 64 cols
#pragma unroll
        for (int p = 0; p < 2; p++) {
            int e = tid + p * 128, r = e >> 3, c = (e & 7) * 8;
            *(uint4*)&Vh[r][c] = *(const uint4*)&g_Vthi[h][r][kt + c];
            *(uint4*)&Vl[r][c] = *(const uint4*)&g_Vtlo[h][r][kt + c];
        }
        __syncthreads();

        // S = Q K^T  (3-term split)
        float s[8][4];
#pragma unroll
        for (int n = 0; n < 8; n++) {
            s[n][0] = s[n][1] = s[n][2] = s[n][3] = 0.0f;
#pragma unroll
            for (int kc = 0; kc < 2; kc++) {
                uint32_t bh0 = *(const uint32_t*)&Kh[n * 8 + r0][kc * 16 + c0];
                uint32_t bh1 = *(const uint32_t*)&Kh[n * 8 + r0][kc * 16 + c0 + 8];
                uint32_t bl0 = *(const uint32_t*)&Kl[n * 8 + r0][kc * 16 + c0];
                uint32_t bl1 = *(const uint32_t*)&Kl[n * 8 + r0][kc * 16 + c0 + 8];
                mma_bf16(s[n], qh[kc], bh0, bh1);
                mma_bf16(s[n], qh[kc], bl0, bl1);
                mma_bf16(s[n], ql[kc], bh0, bh1);
            }
        }
        // add bias, track row max
        float mx[2] = { -1e30f, -1e30f };
#pragma unroll
        for (int n = 0; n < 8; n++) {
            const float* bp = &bias[(size_t)(h * SLEN + q0 + r0) * SLEN + kt + n * 8 + c0];
            float2 b0 = *(const float2*)bp;
            float2 b1 = *(const float2*)(bp + 8 * SLEN);
            s[n][0] += b0.x; s[n][1] += b0.y; s[n][2] += b1.x; s[n][3] += b1.y;
            mx[0] = fmaxf(mx[0], fmaxf(s[n][0], s[n][1]));
            mx[1] = fmaxf(mx[1], fmaxf(s[n][2], s[n][3]));
        }
#pragma unroll
        for (int i = 0; i < 2; i++) {
            mx[i] = fmaxf(mx[i], __shfl_xor_sync(0xffffffffu, mx[i], 1));
            mx[i] = fmaxf(mx[i], __shfl_xor_sync(0xffffffffu, mx[i], 2));
        }
        float mn[2] = { fmaxf(mr[0], mx[0]), fmaxf(mr[1], mx[1]) };
        float rs[2] = { ex2f((mr[0] - mn[0]) * LOG2E), ex2f((mr[1] - mn[1]) * LOG2E) };
        mr[0] = mn[0]; mr[1] = mn[1];
#pragma unroll
        for (int n = 0; n < 4; n++) {
            o[n][0] *= rs[0]; o[n][1] *= rs[0]; o[n][2] *= rs[1]; o[n][3] *= rs[1];
        }
        float sm[2] = { 0.0f, 0.0f };
#pragma unroll
        for (int n = 0; n < 8; n++)
#pragma unroll
            for (int j = 0; j < 4; j++) {
                float p = ex2f((s[n][j] - mn[j >> 1]) * LOG2E);
                s[n][j] = p;
                sm[j >> 1] += p;
            }
#pragma unroll
        for (int i = 0; i < 2; i++) {
            sm[i] += __shfl_xor_sync(0xffffffffu, sm[i], 1);
            sm[i] += __shfl_xor_sync(0xffffffffu, sm[i], 2);
            lr[i] = lr[i] * rs[i] + sm[i];
        }
        // pack P into split bf16 A-fragments
        uint32_t ph[4][4], pl[4][4];
#pragma unroll
        for (int kc = 0; kc < 4; kc++) {
            splitp(s[2 * kc][0],     s[2 * kc][1],     ph[kc][0], pl[kc][0]);
            splitp(s[2 * kc][2],     s[2 * kc][3],     ph[kc][1], pl[kc][1]);
            splitp(s[2 * kc + 1][0], s[2 * kc + 1][1], ph[kc][2], pl[kc][2]);
            splitp(s[2 * kc + 1][2], s[2 * kc + 1][3], ph[kc][3], pl[kc][3]);
        }
        // O += P V  (3-term split)
#pragma unroll
        for (int n = 0; n < 4; n++)
#pragma unroll
            for (int kc = 0; kc < 4; kc++) {
                uint32_t vh0 = *(const uint32_t*)&Vh[n * 8 + r0][kc * 16 + c0];
                uint32_t vh1 = *(const uint32_t*)&Vh[n * 8 + r0][kc * 16 + c0 + 8];
                uint32_t vl0 = *(const uint32_t*)&Vl[n * 8 + r0][kc * 16 + c0];
                uint32_t vl1 = *(const uint32_t*)&Vl[n * 8 + r0][kc * 16 + c0 + 8];
                mma_bf16(o[n], ph[kc], vh0, vh1);
                mma_bf16(o[n], ph[kc], vl0, vl1);
                mma_bf16(o[n], pl[kc], vh0, vh1);
            }
    }
    // epilogue: normalize, gate, store
    float rl0 = 1.0f / lr[0], rl1 = 1.0f / lr[1];
#pragma unroll
    for (int n = 0; n < 4; n++) {
        float2 gg0 = *(const float2*)&g_G[h][q0 + r0][n * 8 + c0];
        float2 gg1 = *(const float2*)&g_G[h][q0 + r0 + 8][n * 8 + c0];
        float2 w0 = { o[n][0] * rl0 * gg0.x, o[n][1] * rl0 * gg0.y };
        float2 w1 = { o[n][2] * rl1 * gg1.x, o[n][3] * rl1 * gg1.y };
        *(float2*)&g_AO[q0 + r0][h * 32 + n * 8 + c0] = w0;
        *(float2*)&g_AO[q0 + r0 + 8][h * 32 + n * 8 + c0] = w1;
    }
}

// =============== kernel 3: output projection (fp32 f32x2) ===============
__global__ __launch_bounds__(128) void outproj_kernel(
    float* __restrict__ out, const float* __restrict__ W, const float* __restrict__ Bv)
{
    __shared__ float As[64][17];
    __shared__ float Bs[16][64];
    const int m0 = blockIdx.y * 64, n0b = blockIdx.x * 64;
    const int tid = threadIdx.x, tx = tid & 15, ty = tid >> 4;

    unsigned long long acc[8][2];
#pragma unroll
    for (int i = 0; i < 8; i++) { acc[i][0] = 0ull; acc[i][1] = 0ull; }

    for (int kt = 0; kt < 256; kt += 16) {
        __syncthreads();
#pragma unroll
        for (int p = 0; p < 2; p++) {
            int e = tid + p * 128, r = e >> 2, kq = e & 3;
            float4 f = *(const float4*)&g_AO[m0 + r][kt + kq * 4];
            As[r][kq * 4 + 0] = f.x; As[r][kq * 4 + 1] = f.y;
            As[r][kq * 4 + 2] = f.z; As[r][kq * 4 + 3] = f.w;
        }
#pragma unroll
        for (int p = 0; p < 2; p++) {
            int e = tid + p * 128, k = e >> 4, nq = e & 15;
            *(float4*)&Bs[k][nq * 4] = *(const float4*)&W[(kt + k) * 256 + n0b + nq * 4];
        }
        __syncthreads();
#pragma unroll
        for (int k = 0; k < 16; k++) {
            unsigned long long b0 = pk2(*(const float2*)&Bs[k][tx * 4]);
            unsigned long long b1 = pk2(*(const float2*)&Bs[k][tx * 4 + 2]);
#pragma unroll
            for (int i = 0; i < 8; i++) {
                unsigned long long a = dup2(As[ty * 8 + i][k]);
                fma2(acc[i][0], a, b0);
                fma2(acc[i][1], a, b1);
            }
        }
    }
#pragma unroll
    for (int i = 0; i < 8; i++) {
        int q = m0 + ty * 8 + i;
#pragma unroll
        for (int j = 0; j < 2; j++) {
            int col = n0b + tx * 4 + j * 2;
            float2 v = unpack2(acc[i][j]);
            v.x += Bv[col]; v.y += Bv[col + 1];
            *(float2*)&out[q * 256 + col] = v;
        }
    }
}

// =============== launch ===============
extern "C" void kernel_launch(void* const* d_in, const int* in_sizes, int n_in,
                              void* d_out, int out_size) {
    const float* q_inputs   = (const float*)d_in[0];
    const float* kv_inputs  = (const float*)d_in[1];
    const float* bias       = (const float*)d_in[2];
    const float* qg_weights = (const float*)d_in[3];
    const float* kv_weights = (const float*)d_in[4];
    const float* qg_bias    = (const float*)d_in[5];
    const float* kv_bias    = (const float*)d_in[6];
    const float* o_weights  = (const float*)d_in[7];
    const float* o_bias     = (const float*)d_in[8];
    float* out = (float*)d_out;

    proj_kernel<<<dim3(8, 32, 2), 128>>>(q_inputs, kv_inputs, qg_weights, kv_weights,
                                         qg_bias, kv_bias);
    attn_kernel<<<dim3(32, 8), 128>>>(bias);
    outproj_kernel<<<dim3(4, 32), 128>>>(out, o_weights, o_bias);
}

// round 5
// speedup vs baseline: 1.1880x; 1.1880x over previous
#include <cuda_runtime.h>
#include <cuda_bf16.h>
#include <stdint.h>

#define NHEAD 8
#define SLEN 2048
#define SCALE 0.17677669529663689f
#define LOG2E 1.4426950408889634f

// ------------- device scratch (no allocation allowed) -------------
static __device__ __align__(16) __nv_bfloat16 g_Qhi[NHEAD][SLEN][32], g_Qlo[NHEAD][SLEN][32];
static __device__ __align__(16) __nv_bfloat16 g_Khi[NHEAD][SLEN][32], g_Klo[NHEAD][SLEN][32];
static __device__ __align__(16) __nv_bfloat16 g_Vthi[NHEAD][32][SLEN], g_Vtlo[NHEAD][32][SLEN];
static __device__ __align__(16) float g_G[NHEAD][SLEN][32];
static __device__ __align__(16) float g_AO[SLEN][256];

// ------------- helpers -------------
__device__ __forceinline__ unsigned long long dup2(float x) {
    unsigned long long r; asm("mov.b64 %0, {%1,%1};" : "=l"(r) : "f"(x)); return r;
}
__device__ __forceinline__ unsigned long long pk2(float2 v) {
    unsigned long long r; asm("mov.b64 %0, {%1,%2};" : "=l"(r) : "f"(v.x), "f"(v.y)); return r;
}
__device__ __forceinline__ void fma2(unsigned long long &d, unsigned long long a, unsigned long long b) {
    asm("fma.rn.f32x2 %0, %1, %2, %0;" : "+l"(d) : "l"(a), "l"(b));
}
__device__ __forceinline__ float2 unpack2(unsigned long long v) {
    float2 r; asm("mov.b64 {%0,%1}, %2;" : "=f"(r.x), "=f"(r.y) : "l"(v)); return r;
}
__device__ __forceinline__ float ex2f(float x) {
    float y; asm("ex2.approx.f32 %0, %1;" : "=f"(y) : "f"(x)); return y;
}
__device__ __forceinline__ uint32_t packbf(float lo, float hi) {
    uint32_t r; asm("cvt.rn.bf16x2.f32 %0, %1, %2;" : "=r"(r) : "f"(hi), "f"(lo)); return r;
}
__device__ __forceinline__ void splitp(float x, float y, uint32_t &hi, uint32_t &lo) {
    hi = packbf(x, y);
    float xh = __uint_as_float(hi << 16);
    float yh = __uint_as_float(hi & 0xffff0000u);
    lo = packbf(x - xh, y - yh);
}
__device__ __forceinline__ void mma_bf16(float* d, const uint32_t* a, uint32_t b0, uint32_t b1) {
    asm volatile("mma.sync.aligned.m16n8k16.row.col.f32.bf16.bf16.f32 "
        "{%0,%1,%2,%3},{%4,%5,%6,%7},{%8,%9},{%0,%1,%2,%3};"
        : "+f"(d[0]), "+f"(d[1]), "+f"(d[2]), "+f"(d[3])
        : "r"(a[0]), "r"(a[1]), "r"(a[2]), "r"(a[3]), "r"(b0), "r"(b1));
}
__device__ __forceinline__ uint32_t smaddr(const void* p) {
    return (uint32_t)__cvta_generic_to_shared(p);
}
__device__ __forceinline__ void cp_async16(uint32_t s, const void* g) {
    asm volatile("cp.async.cg.shared.global [%0], [%1], 16;" :: "r"(s), "l"(g));
}
__device__ __forceinline__ void cp_commit() { asm volatile("cp.async.commit_group;"); }
template<int N> __device__ __forceinline__ void cp_wait() {
    asm volatile("cp.async.wait_group %0;" :: "n"(N));
}

// =============== kernel 1: input projections (fp32 f32x2, double-buffered) ===============
__global__ __launch_bounds__(128) void proj_kernel(
    const float* __restrict__ Xq, const float* __restrict__ Xkv,
    const float* __restrict__ Wq, const float* __restrict__ Wk,
    const float* __restrict__ Bq, const float* __restrict__ Bk)
{
    __shared__ __align__(16) float As[2][64][20];
    __shared__ __align__(16) float Bs[2][16][64];
    const int z = blockIdx.z;
    const float* __restrict__ X  = z ? Xkv : Xq;
    const float* __restrict__ W  = z ? Wk  : Wq;
    const float* __restrict__ Bv = z ? Bk  : Bq;
    const int m0 = blockIdx.y * 64, n0b = blockIdx.x * 64;
    const int tid = threadIdx.x, tx = tid & 15, ty = tid >> 4;

    unsigned long long acc[8][2];
#pragma unroll
    for (int i = 0; i < 8; i++) { acc[i][0] = 0ull; acc[i][1] = 0ull; }

    auto load_stage = [&](int s, int kt) {
#pragma unroll
        for (int p = 0; p < 2; p++) {
            int e = tid + p * 128, r = e >> 2, kq = e & 3;
            cp_async16(smaddr(&As[s][r][kq * 4]), &X[(m0 + r) * 256 + kt + kq * 4]);
        }
#pragma unroll
        for (int p = 0; p < 2; p++) {
            int e = tid + p * 128, k = e >> 4, nq = e & 15;
            cp_async16(smaddr(&Bs[s][k][nq * 4]), &W[(kt + k) * 512 + n0b + nq * 4]);
        }
    };

    load_stage(0, 0); cp_commit();

    for (int it = 0; it < 16; it++) {
        const int buf = it & 1;
        cp_wait<0>();
        __syncthreads();
        if (it + 1 < 16) { load_stage(buf ^ 1, (it + 1) * 16); cp_commit(); }
#pragma unroll
        for (int k = 0; k < 16; k++) {
            unsigned long long b0 = pk2(*(const float2*)&Bs[buf][k][tx * 4]);
            unsigned long long b1 = pk2(*(const float2*)&Bs[buf][k][tx * 4 + 2]);
#pragma unroll
            for (int i = 0; i < 8; i++) {
                unsigned long long a = dup2(As[buf][ty * 8 + i][k]);
                fma2(acc[i][0], a, b0);
                fma2(acc[i][1], a, b1);
            }
        }
        __syncthreads();
    }
#pragma unroll
    for (int i = 0; i < 8; i++) {
        int q = m0 + ty * 8 + i;
#pragma unroll
        for (int j = 0; j < 2; j++) {
            float2 v = unpack2(acc[i][j]);
            float vv[2] = { v.x, v.y };
#pragma unroll
            for (int e = 0; e < 2; e++) {
                int col = n0b + tx * 4 + j * 2 + e;
                int h = col >> 6, cc = col & 63;
                float x = vv[e] + Bv[col];
                if (z == 0) {
                    if (cc < 32) {
                        float s = x * SCALE;
                        __nv_bfloat16 hi = __float2bfloat16(s);
                        g_Qhi[h][q][cc] = hi;
                        g_Qlo[h][q][cc] = __float2bfloat16(s - __bfloat162float(hi));
                    } else {
                        g_G[h][q][cc - 32] = 1.0f / (1.0f + __expf(-x));
                    }
                } else {
                    __nv_bfloat16 hi = __float2bfloat16(x);
                    float lo = x - __bfloat162float(hi);
                    if (cc < 32) {
                        g_Khi[h][q][cc] = hi; g_Klo[h][q][cc] = __float2bfloat16(lo);
                    } else {
                        g_Vthi[h][cc - 32][q] = hi; g_Vtlo[h][cc - 32][q] = __float2bfloat16(lo);
                    }
                }
            }
        }
    }
}

// =============== kernel 2: flash attention (split-bf16 MMA, pipelined) ===============
__global__ __launch_bounds__(128) void attn_kernel(const float* __restrict__ bias)
{
    __shared__ __align__(16) __nv_bfloat16 Kh[2][64][40], Kl[2][64][40];
    __shared__ __align__(16) __nv_bfloat16 Vh[2][32][72], Vl[2][32][72];
    const int h = blockIdx.y;
    const int tid = threadIdx.x, wid = tid >> 5, ln = tid & 31;
    const int q0 = blockIdx.x * 64 + wid * 16;
    const int r0 = ln >> 2, c0 = (ln & 3) * 2;

    auto load_stage = [&](int s, int kt) {
#pragma unroll
        for (int p = 0; p < 2; p++) {
            int e = tid + p * 128, r = e >> 2, c = (e & 3) * 8;
            cp_async16(smaddr(&Kh[s][r][c]), &g_Khi[h][kt + r][c]);
            cp_async16(smaddr(&Kl[s][r][c]), &g_Klo[h][kt + r][c]);
        }
#pragma unroll
        for (int p = 0; p < 2; p++) {
            int e = tid + p * 128, r = e >> 3, c = (e & 7) * 8;
            cp_async16(smaddr(&Vh[s][r][c]), &g_Vthi[h][r][kt + c]);
            cp_async16(smaddr(&Vl[s][r][c]), &g_Vtlo[h][r][kt + c]);
        }
    };

    // Q fragments (hi/lo), 2 k-chunks of 16
    uint32_t qh[2][4], ql[2][4];
#pragma unroll
    for (int kc = 0; kc < 2; kc++) {
        qh[kc][0] = *(const uint32_t*)&g_Qhi[h][q0 + r0][kc * 16 + c0];
        qh[kc][1] = *(const uint32_t*)&g_Qhi[h][q0 + r0 + 8][kc * 16 + c0];
        qh[kc][2] = *(const uint32_t*)&g_Qhi[h][q0 + r0][kc * 16 + c0 + 8];
        qh[kc][3] = *(const uint32_t*)&g_Qhi[h][q0 + r0 + 8][kc * 16 + c0 + 8];
        ql[kc][0] = *(const uint32_t*)&g_Qlo[h][q0 + r0][kc * 16 + c0];
        ql[kc][1] = *(const uint32_t*)&g_Qlo[h][q0 + r0 + 8][kc * 16 + c0];
        ql[kc][2] = *(const uint32_t*)&g_Qlo[h][q0 + r0][kc * 16 + c0 + 8];
        ql[kc][3] = *(const uint32_t*)&g_Qlo[h][q0 + r0 + 8][kc * 16 + c0 + 8];
    }

    float o[4][4];
#pragma unroll
    for (int n = 0; n < 4; n++)
#pragma unroll
        for (int j = 0; j < 4; j++) o[n][j] = 0.0f;
    float mr[2] = { -1e30f, -1e30f };
    float lr[2] = { 0.0f, 0.0f };

    load_stage(0, 0); cp_commit();

    for (int it = 0; it < 32; it++) {
        const int kt = it * 64;
        const int buf = it & 1;
        cp_wait<0>();
        __syncthreads();
        if (it + 1 < 32) { load_stage(buf ^ 1, kt + 64); cp_commit(); }

        // bias prefetch into registers (consumed after QK MMAs)
        float2 bb0[8], bb1[8];
        const float* bp = &bias[(size_t)(h * SLEN + q0 + r0) * SLEN + kt + c0];
#pragma unroll
        for (int n = 0; n < 8; n++) {
            bb0[n] = *(const float2*)(bp + n * 8);
            bb1[n] = *(const float2*)(bp + 8 * SLEN + n * 8);
        }

        // S = Q K^T  (3-term split)
        float s[8][4];
#pragma unroll
        for (int n = 0; n < 8; n++) {
            s[n][0] = s[n][1] = s[n][2] = s[n][3] = 0.0f;
#pragma unroll
            for (int kc = 0; kc < 2; kc++) {
                uint32_t bh0 = *(const uint32_t*)&Kh[buf][n * 8 + r0][kc * 16 + c0];
                uint32_t bh1 = *(const uint32_t*)&Kh[buf][n * 8 + r0][kc * 16 + c0 + 8];
                uint32_t bl0 = *(const uint32_t*)&Kl[buf][n * 8 + r0][kc * 16 + c0];
                uint32_t bl1 = *(const uint32_t*)&Kl[buf][n * 8 + r0][kc * 16 + c0 + 8];
                mma_bf16(s[n], qh[kc], bh0, bh1);
                mma_bf16(s[n], qh[kc], bl0, bl1);
                mma_bf16(s[n], ql[kc], bh0, bh1);
            }
        }
        // add bias, track row max
        float mx[2] = { -1e30f, -1e30f };
#pragma unroll
        for (int n = 0; n < 8; n++) {
            s[n][0] += bb0[n].x; s[n][1] += bb0[n].y;
            s[n][2] += bb1[n].x; s[n][3] += bb1[n].y;
            mx[0] = fmaxf(mx[0], fmaxf(s[n][0], s[n][1]));
            mx[1] = fmaxf(mx[1], fmaxf(s[n][2], s[n][3]));
        }
#pragma unroll
        for (int i = 0; i < 2; i++) {
            mx[i] = fmaxf(mx[i], __shfl_xor_sync(0xffffffffu, mx[i], 1));
            mx[i] = fmaxf(mx[i], __shfl_xor_sync(0xffffffffu, mx[i], 2));
        }
        float mn[2] = { fmaxf(mr[0], mx[0]), fmaxf(mr[1], mx[1]) };
        float rs[2] = { ex2f((mr[0] - mn[0]) * LOG2E), ex2f((mr[1] - mn[1]) * LOG2E) };
        mr[0] = mn[0]; mr[1] = mn[1];
#pragma unroll
        for (int n = 0; n < 4; n++) {
            o[n][0] *= rs[0]; o[n][1] *= rs[0]; o[n][2] *= rs[1]; o[n][3] *= rs[1];
        }
        float sm[2] = { 0.0f, 0.0f };
#pragma unroll
        for (int n = 0; n < 8; n++)
#pragma unroll
            for (int j = 0; j < 4; j++) {
                float p = ex2f((s[n][j] - mn[j >> 1]) * LOG2E);
                s[n][j] = p;
                sm[j >> 1] += p;
            }
#pragma unroll
        for (int i = 0; i < 2; i++) {
            sm[i] += __shfl_xor_sync(0xffffffffu, sm[i], 1);
            sm[i] += __shfl_xor_sync(0xffffffffu, sm[i], 2);
            lr[i] = lr[i] * rs[i] + sm[i];
        }
        // pack P into split bf16 A-fragments
        uint32_t ph[4][4], pl[4][4];
#pragma unroll
        for (int kc = 0; kc < 4; kc++) {
            splitp(s[2 * kc][0],     s[2 * kc][1],     ph[kc][0], pl[kc][0]);
            splitp(s[2 * kc][2],     s[2 * kc][3],     ph[kc][1], pl[kc][1]);
            splitp(s[2 * kc + 1][0], s[2 * kc + 1][1], ph[kc][2], pl[kc][2]);
            splitp(s[2 * kc + 1][2], s[2 * kc + 1][3], ph[kc][3], pl[kc][3]);
        }
        // O += P V  (3-term split)
#pragma unroll
        for (int n = 0; n < 4; n++)
#pragma unroll
            for (int kc = 0; kc < 4; kc++) {
                uint32_t vh0 = *(const uint32_t*)&Vh[buf][n * 8 + r0][kc * 16 + c0];
                uint32_t vh1 = *(const uint32_t*)&Vh[buf][n * 8 + r0][kc * 16 + c0 + 8];
                uint32_t vl0 = *(const uint32_t*)&Vl[buf][n * 8 + r0][kc * 16 + c0];
                uint32_t vl1 = *(const uint32_t*)&Vl[buf][n * 8 + r0][kc * 16 + c0 + 8];
                mma_bf16(o[n], ph[kc], vh0, vh1);
                mma_bf16(o[n], ph[kc], vl0, vl1);
                mma_bf16(o[n], pl[kc], vh0, vh1);
            }
    }
    // epilogue: normalize, gate, store
    float rl0 = 1.0f / lr[0], rl1 = 1.0f / lr[1];
#pragma unroll
    for (int n = 0; n < 4; n++) {
        float2 gg0 = *(const float2*)&g_G[h][q0 + r0][n * 8 + c0];
        float2 gg1 = *(const float2*)&g_G[h][q0 + r0 + 8][n * 8 + c0];
        float2 w0 = { o[n][0] * rl0 * gg0.x, o[n][1] * rl0 * gg0.y };
        float2 w1 = { o[n][2] * rl1 * gg1.x, o[n][3] * rl1 * gg1.y };
        *(float2*)&g_AO[q0 + r0][h * 32 + n * 8 + c0] = w0;
        *(float2*)&g_AO[q0 + r0 + 8][h * 32 + n * 8 + c0] = w1;
    }
}

// =============== kernel 3: output projection (fp32 f32x2, double-buffered) ===============
__global__ __launch_bounds__(128) void outproj_kernel(
    float* __restrict__ out, const float* __restrict__ W, const float* __restrict__ Bv)
{
    __shared__ __align__(16) float As[2][64][20];
    __shared__ __align__(16) float Bs[2][16][64];
    const int m0 = blockIdx.y * 64, n0b = blockIdx.x * 64;
    const int tid = threadIdx.x, tx = tid & 15, ty = tid >> 4;

    unsigned long long acc[8][2];
#pragma unroll
    for (int i = 0; i < 8; i++) { acc[i][0] = 0ull; acc[i][1] = 0ull; }

    auto load_stage = [&](int s, int kt) {
#pragma unroll
        for (int p = 0; p < 2; p++) {
            int e = tid + p * 128, r = e >> 2, kq = e & 3;
            cp_async16(smaddr(&As[s][r][kq * 4]), &g_AO[m0 + r][kt + kq * 4]);
        }
#pragma unroll
        for (int p = 0; p < 2; p++) {
            int e = tid + p * 128, k = e >> 4, nq = e & 15;
            cp_async16(smaddr(&Bs[s][k][nq * 4]), &W[(kt + k) * 256 + n0b + nq * 4]);
        }
    };

    load_stage(0, 0); cp_commit();

    for (int it = 0; it < 16; it++) {
        const int buf = it & 1;
        cp_wait<0>();
        __syncthreads();
        if (it + 1 < 16) { load_stage(buf ^ 1, (it + 1) * 16); cp_commit(); }
#pragma unroll
        for (int k = 0; k < 16; k++) {
            unsigned long long b0 = pk2(*(const float2*)&Bs[buf][k][tx * 4]);
            unsigned long long b1 = pk2(*(const float2*)&Bs[buf][k][tx * 4 + 2]);
#pragma unroll
            for (int i = 0; i < 8; i++) {
                unsigned long long a = dup2(As[buf][ty * 8 + i][k]);
                fma2(acc[i][0], a, b0);
                fma2(acc[i][1], a, b1);
            }
        }
        __syncthreads();
    }
#pragma unroll
    for (int i = 0; i < 8; i++) {
        int q = m0 + ty * 8 + i;
#pragma unroll
        for (int j = 0; j < 2; j++) {
            int col = n0b + tx * 4 + j * 2;
            float2 v = unpack2(acc[i][j]);
            v.x += Bv[col]; v.y += Bv[col + 1];
            *(float2*)&out[q * 256 + col] = v;
        }
    }
}

// =============== launch ===============
extern "C" void kernel_launch(void* const* d_in, const int* in_sizes, int n_in,
                              void* d_out, int out_size) {
    const float* q_inputs   = (const float*)d_in[0];
    const float* kv_inputs  = (const float*)d_in[1];
    const float* bias       = (const float*)d_in[2];
    const float* qg_weights = (const float*)d_in[3];
    const float* kv_weights = (const float*)d_in[4];
    const float* qg_bias    = (const float*)d_in[5];
    const float* kv_bias    = (const float*)d_in[6];
    const float* o_weights  = (const float*)d_in[7];
    const float* o_bias     = (const float*)d_in[8];
    float* out = (float*)d_out;

    proj_kernel<<<dim3(8, 32, 2), 128>>>(q_inputs, kv_inputs, qg_weights, kv_weights,
                                         qg_bias, kv_bias);
    attn_kernel<<<dim3(32, 8), 128>>>(bias);
    outproj_kernel<<<dim3(4, 32), 128>>>(out, o_weights, o_bias);
}

// round 6
// speedup vs baseline: 1.2849x; 1.0815x over previous
#include <cuda_runtime.h>
#include <cuda_bf16.h>
#include <stdint.h>

#define NHEAD 8
#define SLEN 2048
#define SCALE 0.17677669529663689f
#define LOG2E 1.4426950408889634f

// ------------- device scratch (no allocation allowed) -------------
static __device__ __align__(16) __nv_bfloat16 g_Qhi[NHEAD][SLEN][32], g_Qlo[NHEAD][SLEN][32];
static __device__ __align__(16) __nv_bfloat16 g_Khi[NHEAD][SLEN][32], g_Klo[NHEAD][SLEN][32];
static __device__ __align__(16) __nv_bfloat16 g_Vthi[NHEAD][32][SLEN], g_Vtlo[NHEAD][32][SLEN];
static __device__ __align__(16) float g_G[NHEAD][SLEN][32];
static __device__ __align__(16) float g_AO[SLEN][256];
// split-K partials: unnormalized O, plus (m, l) per row
static __device__ __align__(16) float g_Opart[2][NHEAD][SLEN][32];
static __device__ __align__(16) float g_ml[2][NHEAD][SLEN][2];

// ------------- helpers -------------
__device__ __forceinline__ unsigned long long dup2(float x) {
    unsigned long long r; asm("mov.b64 %0, {%1,%1};" : "=l"(r) : "f"(x)); return r;
}
__device__ __forceinline__ unsigned long long pk2(float2 v) {
    unsigned long long r; asm("mov.b64 %0, {%1,%2};" : "=l"(r) : "f"(v.x), "f"(v.y)); return r;
}
__device__ __forceinline__ void fma2(unsigned long long &d, unsigned long long a, unsigned long long b) {
    asm("fma.rn.f32x2 %0, %1, %2, %0;" : "+l"(d) : "l"(a), "l"(b));
}
__device__ __forceinline__ float2 unpack2(unsigned long long v) {
    float2 r; asm("mov.b64 {%0,%1}, %2;" : "=f"(r.x), "=f"(r.y) : "l"(v)); return r;
}
__device__ __forceinline__ float ex2f(float x) {
    float y; asm("ex2.approx.f32 %0, %1;" : "=f"(y) : "f"(x)); return y;
}
__device__ __forceinline__ uint32_t packbf(float lo, float hi) {
    uint32_t r; asm("cvt.rn.bf16x2.f32 %0, %1, %2;" : "=r"(r) : "f"(hi), "f"(lo)); return r;
}
__device__ __forceinline__ void splitp(float x, float y, uint32_t &hi, uint32_t &lo) {
    hi = packbf(x, y);
    float xh = __uint_as_float(hi << 16);
    float yh = __uint_as_float(hi & 0xffff0000u);
    lo = packbf(x - xh, y - yh);
}
__device__ __forceinline__ void mma_bf16(float* d, const uint32_t* a, uint32_t b0, uint32_t b1) {
    asm volatile("mma.sync.aligned.m16n8k16.row.col.f32.bf16.bf16.f32 "
        "{%0,%1,%2,%3},{%4,%5,%6,%7},{%8,%9},{%0,%1,%2,%3};"
        : "+f"(d[0]), "+f"(d[1]), "+f"(d[2]), "+f"(d[3])
        : "r"(a[0]), "r"(a[1]), "r"(a[2]), "r"(a[3]), "r"(b0), "r"(b1));
}
__device__ __forceinline__ uint32_t smaddr(const void* p) {
    return (uint32_t)__cvta_generic_to_shared(p);
}
__device__ __forceinline__ void cp_async16(uint32_t s, const void* g) {
    asm volatile("cp.async.cg.shared.global [%0], [%1], 16;" :: "r"(s), "l"(g));
}
__device__ __forceinline__ void cp_commit() { asm volatile("cp.async.commit_group;"); }
template<int N> __device__ __forceinline__ void cp_wait() {
    asm volatile("cp.async.wait_group %0;" :: "n"(N));
}

// =============== kernel 1: input projections (fp32 f32x2, double-buffered) ===============
__global__ __launch_bounds__(128) void proj_kernel(
    const float* __restrict__ Xq, const float* __restrict__ Xkv,
    const float* __restrict__ Wq, const float* __restrict__ Wk,
    const float* __restrict__ Bq, const float* __restrict__ Bk)
{
    __shared__ __align__(16) float As[2][64][20];
    __shared__ __align__(16) float Bs[2][16][64];
    const int z = blockIdx.z;
    const float* __restrict__ X  = z ? Xkv : Xq;
    const float* __restrict__ W  = z ? Wk  : Wq;
    const float* __restrict__ Bv = z ? Bk  : Bq;
    const int m0 = blockIdx.y * 64, n0b = blockIdx.x * 64;
    const int tid = threadIdx.x, tx = tid & 15, ty = tid >> 4;

    unsigned long long acc[8][2];
#pragma unroll
    for (int i = 0; i < 8; i++) { acc[i][0] = 0ull; acc[i][1] = 0ull; }

    auto load_stage = [&](int s, int kt) {
#pragma unroll
        for (int p = 0; p < 2; p++) {
            int e = tid + p * 128, r = e >> 2, kq = e & 3;
            cp_async16(smaddr(&As[s][r][kq * 4]), &X[(m0 + r) * 256 + kt + kq * 4]);
        }
#pragma unroll
        for (int p = 0; p < 2; p++) {
            int e = tid + p * 128, k = e >> 4, nq = e & 15;
            cp_async16(smaddr(&Bs[s][k][nq * 4]), &W[(kt + k) * 512 + n0b + nq * 4]);
        }
    };

    load_stage(0, 0); cp_commit();

    for (int it = 0; it < 16; it++) {
        const int buf = it & 1;
        cp_wait<0>();
        __syncthreads();
        if (it + 1 < 16) { load_stage(buf ^ 1, (it + 1) * 16); cp_commit(); }
#pragma unroll
        for (int k = 0; k < 16; k++) {
            unsigned long long b0 = pk2(*(const float2*)&Bs[buf][k][tx * 4]);
            unsigned long long b1 = pk2(*(const float2*)&Bs[buf][k][tx * 4 + 2]);
#pragma unroll
            for (int i = 0; i < 8; i++) {
                unsigned long long a = dup2(As[buf][ty * 8 + i][k]);
                fma2(acc[i][0], a, b0);
                fma2(acc[i][1], a, b1);
            }
        }
        __syncthreads();
    }
#pragma unroll
    for (int i = 0; i < 8; i++) {
        int q = m0 + ty * 8 + i;
#pragma unroll
        for (int j = 0; j < 2; j++) {
            float2 v = unpack2(acc[i][j]);
            float vv[2] = { v.x, v.y };
#pragma unroll
            for (int e = 0; e < 2; e++) {
                int col = n0b + tx * 4 + j * 2 + e;
                int h = col >> 6, cc = col & 63;
                float x = vv[e] + Bv[col];
                if (z == 0) {
                    if (cc < 32) {
                        float s = x * SCALE;
                        __nv_bfloat16 hi = __float2bfloat16(s);
                        g_Qhi[h][q][cc] = hi;
                        g_Qlo[h][q][cc] = __float2bfloat16(s - __bfloat162float(hi));
                    } else {
                        g_G[h][q][cc - 32] = 1.0f / (1.0f + __expf(-x));
                    }
                } else {
                    __nv_bfloat16 hi = __float2bfloat16(x);
                    float lo = x - __bfloat162float(hi);
                    if (cc < 32) {
                        g_Khi[h][q][cc] = hi; g_Klo[h][q][cc] = __float2bfloat16(lo);
                    } else {
                        g_Vthi[h][cc - 32][q] = hi; g_Vtlo[h][cc - 32][q] = __float2bfloat16(lo);
                    }
                }
            }
        }
    }
}

// =============== kernel 2: flash attention, split-K (split-bf16 MMA) ===============
// blockIdx.z = k-half: this block processes k-tiles (2*it + z)*64, it in [0,16)
__global__ __launch_bounds__(128) void attn_kernel(const float* __restrict__ bias)
{
    __shared__ __align__(16) __nv_bfloat16 Kh[2][64][40], Kl[2][64][40];
    __shared__ __align__(16) __nv_bfloat16 Vh[2][32][72], Vl[2][32][72];
    const int h = blockIdx.y;
    const int z = blockIdx.z;
    const int tid = threadIdx.x, wid = tid >> 5, ln = tid & 31;
    const int q0 = blockIdx.x * 64 + wid * 16;
    const int r0 = ln >> 2, c0 = (ln & 3) * 2;

    auto load_stage = [&](int s, int kt) {
#pragma unroll
        for (int p = 0; p < 2; p++) {
            int e = tid + p * 128, r = e >> 2, c = (e & 3) * 8;
            cp_async16(smaddr(&Kh[s][r][c]), &g_Khi[h][kt + r][c]);
            cp_async16(smaddr(&Kl[s][r][c]), &g_Klo[h][kt + r][c]);
        }
#pragma unroll
        for (int p = 0; p < 2; p++) {
            int e = tid + p * 128, r = e >> 3, c = (e & 7) * 8;
            cp_async16(smaddr(&Vh[s][r][c]), &g_Vthi[h][r][kt + c]);
            cp_async16(smaddr(&Vl[s][r][c]), &g_Vtlo[h][r][kt + c]);
        }
    };

    // Q fragments (hi/lo), 2 k-chunks of 16
    uint32_t qh[2][4], ql[2][4];
#pragma unroll
    for (int kc = 0; kc < 2; kc++) {
        qh[kc][0] = *(const uint32_t*)&g_Qhi[h][q0 + r0][kc * 16 + c0];
        qh[kc][1] = *(const uint32_t*)&g_Qhi[h][q0 + r0 + 8][kc * 16 + c0];
        qh[kc][2] = *(const uint32_t*)&g_Qhi[h][q0 + r0][kc * 16 + c0 + 8];
        qh[kc][3] = *(const uint32_t*)&g_Qhi[h][q0 + r0 + 8][kc * 16 + c0 + 8];
        ql[kc][0] = *(const uint32_t*)&g_Qlo[h][q0 + r0][kc * 16 + c0];
        ql[kc][1] = *(const uint32_t*)&g_Qlo[h][q0 + r0 + 8][kc * 16 + c0];
        ql[kc][2] = *(const uint32_t*)&g_Qlo[h][q0 + r0][kc * 16 + c0 + 8];
        ql[kc][3] = *(const uint32_t*)&g_Qlo[h][q0 + r0 + 8][kc * 16 + c0 + 8];
    }

    float o[4][4];
#pragma unroll
    for (int n = 0; n < 4; n++)
#pragma unroll
        for (int j = 0; j < 4; j++) o[n][j] = 0.0f;
    float mr[2] = { -1e30f, -1e30f };
    float lr[2] = { 0.0f, 0.0f };

    load_stage(0, z * 64); cp_commit();

    for (int it = 0; it < 16; it++) {
        const int kt = (it * 2 + z) * 64;
        const int buf = it & 1;
        cp_wait<0>();
        __syncthreads();
        if (it + 1 < 16) { load_stage(buf ^ 1, kt + 128); cp_commit(); }

        // bias prefetch into registers (consumed after QK MMAs)
        float2 bb0[8], bb1[8];
        const float* bp = &bias[(size_t)(h * SLEN + q0 + r0) * SLEN + kt + c0];
#pragma unroll
        for (int n = 0; n < 8; n++) {
            bb0[n] = *(const float2*)(bp + n * 8);
            bb1[n] = *(const float2*)(bp + 8 * SLEN + n * 8);
        }

        // S = Q K^T  (3-term split)
        float s[8][4];
#pragma unroll
        for (int n = 0; n < 8; n++) {
            s[n][0] = s[n][1] = s[n][2] = s[n][3] = 0.0f;
#pragma unroll
            for (int kc = 0; kc < 2; kc++) {
                uint32_t bh0 = *(const uint32_t*)&Kh[buf][n * 8 + r0][kc * 16 + c0];
                uint32_t bh1 = *(const uint32_t*)&Kh[buf][n * 8 + r0][kc * 16 + c0 + 8];
                uint32_t bl0 = *(const uint32_t*)&Kl[buf][n * 8 + r0][kc * 16 + c0];
                uint32_t bl1 = *(const uint32_t*)&Kl[buf][n * 8 + r0][kc * 16 + c0 + 8];
                mma_bf16(s[n], qh[kc], bh0, bh1);
                mma_bf16(s[n], qh[kc], bl0, bl1);
                mma_bf16(s[n], ql[kc], bh0, bh1);
            }
        }
        // add bias, track row max
        float mx[2] = { -1e30f, -1e30f };
#pragma unroll
        for (int n = 0; n < 8; n++) {
            s[n][0] += bb0[n].x; s[n][1] += bb0[n].y;
            s[n][2] += bb1[n].x; s[n][3] += bb1[n].y;
            mx[0] = fmaxf(mx[0], fmaxf(s[n][0], s[n][1]));
            mx[1] = fmaxf(mx[1], fmaxf(s[n][2], s[n][3]));
        }
#pragma unroll
        for (int i = 0; i < 2; i++) {
            mx[i] = fmaxf(mx[i], __shfl_xor_sync(0xffffffffu, mx[i], 1));
            mx[i] = fmaxf(mx[i], __shfl_xor_sync(0xffffffffu, mx[i], 2));
        }
        float mn[2] = { fmaxf(mr[0], mx[0]), fmaxf(mr[1], mx[1]) };
        float rs[2] = { ex2f((mr[0] - mn[0]) * LOG2E), ex2f((mr[1] - mn[1]) * LOG2E) };
        mr[0] = mn[0]; mr[1] = mn[1];
#pragma unroll
        for (int n = 0; n < 4; n++) {
            o[n][0] *= rs[0]; o[n][1] *= rs[0]; o[n][2] *= rs[1]; o[n][3] *= rs[1];
        }
        float sm[2] = { 0.0f, 0.0f };
#pragma unroll
        for (int n = 0; n < 8; n++)
#pragma unroll
            for (int j = 0; j < 4; j++) {
                float p = ex2f((s[n][j] - mn[j >> 1]) * LOG2E);
                s[n][j] = p;
                sm[j >> 1] += p;
            }
#pragma unroll
        for (int i = 0; i < 2; i++) {
            sm[i] += __shfl_xor_sync(0xffffffffu, sm[i], 1);
            sm[i] += __shfl_xor_sync(0xffffffffu, sm[i], 2);
            lr[i] = lr[i] * rs[i] + sm[i];
        }
        // pack P into split bf16 A-fragments
        uint32_t ph[4][4], pl[4][4];
#pragma unroll
        for (int kc = 0; kc < 4; kc++) {
            splitp(s[2 * kc][0],     s[2 * kc][1],     ph[kc][0], pl[kc][0]);
            splitp(s[2 * kc][2],     s[2 * kc][3],     ph[kc][1], pl[kc][1]);
            splitp(s[2 * kc + 1][0], s[2 * kc + 1][1], ph[kc][2], pl[kc][2]);
            splitp(s[2 * kc + 1][2], s[2 * kc + 1][3], ph[kc][3], pl[kc][3]);
        }
        // O += P V  (3-term split)
#pragma unroll
        for (int n = 0; n < 4; n++)
#pragma unroll
            for (int kc = 0; kc < 4; kc++) {
                uint32_t vh0 = *(const uint32_t*)&Vh[buf][n * 8 + r0][kc * 16 + c0];
                uint32_t vh1 = *(const uint32_t*)&Vh[buf][n * 8 + r0][kc * 16 + c0 + 8];
                uint32_t vl0 = *(const uint32_t*)&Vl[buf][n * 8 + r0][kc * 16 + c0];
                uint32_t vl1 = *(const uint32_t*)&Vl[buf][n * 8 + r0][kc * 16 + c0 + 8];
                mma_bf16(o[n], ph[kc], vh0, vh1);
                mma_bf16(o[n], ph[kc], vl0, vl1);
                mma_bf16(o[n], pl[kc], vh0, vh1);
            }
    }
    // epilogue: write unnormalized partials (O, m, l)
#pragma unroll
    for (int n = 0; n < 4; n++) {
        float2 w0 = { o[n][0], o[n][1] };
        float2 w1 = { o[n][2], o[n][3] };
        *(float2*)&g_Opart[z][h][q0 + r0][n * 8 + c0] = w0;
        *(float2*)&g_Opart[z][h][q0 + r0 + 8][n * 8 + c0] = w1;
    }
    if ((ln & 3) == 0) {
        g_ml[z][h][q0 + r0][0] = mr[0];
        g_ml[z][h][q0 + r0][1] = lr[0];
        g_ml[z][h][q0 + r0 + 8][0] = mr[1];
        g_ml[z][h][q0 + r0 + 8][1] = lr[1];
    }
}

// =============== kernel 2b: split-K merge + gate ===============
__global__ __launch_bounds__(256) void merge_kernel()
{
    int t = blockIdx.x * 256 + threadIdx.x;   // one (h, q) row per thread
    int h = t >> 11, q = t & 2047;
    float m0 = g_ml[0][h][q][0], l0 = g_ml[0][h][q][1];
    float m1 = g_ml[1][h][q][0], l1 = g_ml[1][h][q][1];
    float m = fmaxf(m0, m1);
    float f0 = ex2f((m0 - m) * LOG2E);
    float f1 = ex2f((m1 - m) * LOG2E);
    float rl = 1.0f / (l0 * f0 + l1 * f1);
    float a0 = f0 * rl, a1 = f1 * rl;
#pragma unroll
    for (int c = 0; c < 32; c += 4) {
        float4 x0 = *(const float4*)&g_Opart[0][h][q][c];
        float4 x1 = *(const float4*)&g_Opart[1][h][q][c];
        float4 gg = *(const float4*)&g_G[h][q][c];
        float4 r;
        r.x = (x0.x * a0 + x1.x * a1) * gg.x;
        r.y = (x0.y * a0 + x1.y * a1) * gg.y;
        r.z = (x0.z * a0 + x1.z * a1) * gg.z;
        r.w = (x0.w * a0 + x1.w * a1) * gg.w;
        *(float4*)&g_AO[q][h * 32 + c] = r;
    }
}

// =============== kernel 3: output projection (fp32 f32x2, double-buffered) ===============
__global__ __launch_bounds__(128) void outproj_kernel(
    float* __restrict__ out, const float* __restrict__ W, const float* __restrict__ Bv)
{
    __shared__ __align__(16) float As[2][64][20];
    __shared__ __align__(16) float Bs[2][16][64];
    const int m0 = blockIdx.y * 64, n0b = blockIdx.x * 64;
    const int tid = threadIdx.x, tx = tid & 15, ty = tid >> 4;

    unsigned long long acc[8][2];
#pragma unroll
    for (int i = 0; i < 8; i++) { acc[i][0] = 0ull; acc[i][1] = 0ull; }

    auto load_stage = [&](int s, int kt) {
#pragma unroll
        for (int p = 0; p < 2; p++) {
            int e = tid + p * 128, r = e >> 2, kq = e & 3;
            cp_async16(smaddr(&As[s][r][kq * 4]), &g_AO[m0 + r][kt + kq * 4]);
        }
#pragma unroll
        for (int p = 0; p < 2; p++) {
            int e = tid + p * 128, k = e >> 4, nq = e & 15;
            cp_async16(smaddr(&Bs[s][k][nq * 4]), &W[(kt + k) * 256 + n0b + nq * 4]);
        }
    };

    load_stage(0, 0); cp_commit();

    for (int it = 0; it < 16; it++) {
        const int buf = it & 1;
        cp_wait<0>();
        __syncthreads();
        if (it + 1 < 16) { load_stage(buf ^ 1, (it + 1) * 16); cp_commit(); }
#pragma unroll
        for (int k = 0; k < 16; k++) {
            unsigned long long b0 = pk2(*(const float2*)&Bs[buf][k][tx * 4]);
            unsigned long long b1 = pk2(*(const float2*)&Bs[buf][k][tx * 4 + 2]);
#pragma unroll
            for (int i = 0; i < 8; i++) {
                unsigned long long a = dup2(As[buf][ty * 8 + i][k]);
                fma2(acc[i][0], a, b0);
                fma2(acc[i][1], a, b1);
            }
        }
        __syncthreads();
    }
#pragma unroll
    for (int i = 0; i < 8; i++) {
        int q = m0 + ty * 8 + i;
#pragma unroll
        for (int j = 0; j < 2; j++) {
            int col = n0b + tx * 4 + j * 2;
            float2 v = unpack2(acc[i][j]);
            v.x += Bv[col]; v.y += Bv[col + 1];
            *(float2*)&out[q * 256 + col] = v;
        }
    }
}

// =============== launch ===============
extern "C" void kernel_launch(void* const* d_in, const int* in_sizes, int n_in,
                              void* d_out, int out_size) {
    const float* q_inputs   = (const float*)d_in[0];
    const float* kv_inputs  = (const float*)d_in[1];
    const float* bias       = (const float*)d_in[2];
    const float* qg_weights = (const float*)d_in[3];
    const float* kv_weights = (const float*)d_in[4];
    const float* qg_bias    = (const float*)d_in[5];
    const float* kv_bias    = (const float*)d_in[6];
    const float* o_weights  = (const float*)d_in[7];
    const float* o_bias     = (const float*)d_in[8];
    float* out = (float*)d_out;

    proj_kernel<<<dim3(8, 32, 2), 128>>>(q_inputs, kv_inputs, qg_weights, kv_weights,
                                         qg_bias, kv_bias);
    attn_kernel<<<dim3(32, 8, 2), 128>>>(bias);
    merge_kernel<<<64, 256>>>();
    outproj_kernel<<<dim3(4, 32), 128>>>(out, o_weights, o_bias);
}